// round 15
// baseline (speedup 1.0000x reference)
#include <cuda_runtime.h>
#include <cuda_bf16.h>
#include <cuda_fp16.h>
#include <math.h>
#include <stdint.h>

#define NN 100000
#define EE 3200000
#define FIN 512
#define HH 256
#define CC 64
#define LL 8
#define ALPHA 0.1f
#define SCL 0.0625f                     // per-layer storage scale s = 1/16
#define UNSCALE 4294967296.0f           // s^-8 = 2^32 (exact fp32)

#define NCHUNKS_TOT 40
#define CHUNK_ELEMS 16384

// ---------------- scratch (no cudaMalloc allowed) ----------------
__device__ __align__(16) __half g_hhA[(size_t)NN * HH];
__device__ __align__(16) __half g_hhB[(size_t)NN * HH];
__device__ __align__(16) __half g_x0h[(size_t)NN * HH];
__device__ int    g_rowptr[NN + 1];
__device__ int    g_cnt[NN];
__device__ int    g_col[EE];
__device__ float  g_val[EE];
__device__ __align__(16) uint16_t g_Bh[(size_t)NCHUNKS_TOT * CHUNK_ELEMS];
__device__ __align__(16) uint16_t g_Bl[(size_t)NCHUNKS_TOT * CHUNK_ELEMS];

// ---------------------------------------------------------------------------
__device__ __forceinline__ uint16_t bf16_bits(float v) {
    __nv_bfloat16 b = __float2bfloat16_rn(v);
    return *reinterpret_cast<uint16_t*>(&b);
}
__device__ __forceinline__ float bf16_val(uint16_t u) {
    __nv_bfloat16 b = *reinterpret_cast<__nv_bfloat16*>(&u);
    return __bfloat162float(b);
}

__device__ __forceinline__ void mma16816(float* d, const uint32_t* a,
                                         uint32_t b0, uint32_t b1) {
    asm volatile(
        "mma.sync.aligned.m16n8k16.row.col.f32.bf16.bf16.f32 "
        "{%0,%1,%2,%3}, {%4,%5,%6,%7}, {%8,%9}, {%0,%1,%2,%3};"
        : "+f"(d[0]), "+f"(d[1]), "+f"(d[2]), "+f"(d[3])
        : "r"(a[0]), "r"(a[1]), "r"(a[2]), "r"(a[3]), "r"(b0), "r"(b1));
}

// ---------------------------------------------------------------------------
// B chunk library: chunks 0..7 = W_in (K=512); 8+4l+c = beta*W_l + (1-beta)I.
// ---------------------------------------------------------------------------
__global__ void prep_B_kernel(const float* __restrict__ Win,
                              const float* __restrict__ convW,
                              uint16_t* __restrict__ Bh, uint16_t* __restrict__ Bl)
{
    int e = blockIdx.x * 256 + threadIdx.x;
    if (e >= NCHUNKS_TOT * CHUNK_ELEMS) return;
    int chunk = e >> 14, w = e & 16383;
    int n = w >> 6, kk = w & 63;
    float val;
    if (chunk < 8) {
        val = __ldg(&Win[(chunk * 64 + kk) * HH + n]);
    } else {
        int l = (chunk - 8) >> 2, c = (chunk - 8) & 3, k = c * 64 + kk;
        float beta = logf(0.5f / (float)(l + 1) + 1.0f);
        val = beta * __ldg(&convW[(size_t)l * HH * HH + (size_t)k * HH + n]);
        if (k == n) val += 1.0f - beta;
    }
    uint16_t hi = bf16_bits(val);
    uint16_t lo = bf16_bits(val - bf16_val(hi));
    Bh[e] = hi;
    Bl[e] = lo;
}

// ---------------------------------------------------------------------------
// Input GEMM (fp32 A from gmem): Ch = relu(A @ Bchunks + bias) in fp16,
// C2 (fp16 x0 copy) dual-write.  BM=BN=128, 256 threads, as in R11.
// ---------------------------------------------------------------------------
#define LDP 72
#define SA_ELEMS (128 * LDP)
__global__ __launch_bounds__(256, 2)
void mma_gemm_in(const float* __restrict__ A,
                 const uint16_t* __restrict__ Bh, const uint16_t* __restrict__ Bl,
                 const float* __restrict__ bias,
                 __half* __restrict__ Ch, __half* __restrict__ C2, int M)
{
    extern __shared__ uint16_t sm[];
    uint16_t* sAh = sm;
    uint16_t* sAl = sm + SA_ELEMS;
    uint16_t* sBh = sm + 2 * SA_ELEMS;
    uint16_t* sBl = sm + 3 * SA_ELEMS;

    const int tid = threadIdx.x;
    const int warp = tid >> 5, lane = tid & 31;
    const int wm = warp >> 1, wn = warp & 1;
    const int g = lane >> 2, t = lane & 3;
    const int row0 = blockIdx.y * 128;
    const int col0 = blockIdx.x * 128;

    float acc[2][8][4];
#pragma unroll
    for (int mi = 0; mi < 2; mi++)
#pragma unroll
        for (int ni = 0; ni < 8; ni++)
#pragma unroll
            for (int q = 0; q < 4; q++) acc[mi][ni][q] = 0.f;

    for (int c = 0; c < 8; c++) {
        __syncthreads();
#pragma unroll
        for (int i = 0; i < 8; i++) {
            int f = tid + i * 256;
            int r = f >> 4, kq = (f & 15) * 4;
            float4 v = make_float4(0.f, 0.f, 0.f, 0.f);
            if (row0 + r < M)
                v = *(const float4*)(A + (size_t)(row0 + r) * FIN + c * 64 + kq);
            uint16_t h0 = bf16_bits(v.x), h1 = bf16_bits(v.y);
            uint16_t h2 = bf16_bits(v.z), h3 = bf16_bits(v.w);
            uint16_t l0 = bf16_bits(v.x - bf16_val(h0));
            uint16_t l1 = bf16_bits(v.y - bf16_val(h1));
            uint16_t l2 = bf16_bits(v.z - bf16_val(h2));
            uint16_t l3 = bf16_bits(v.w - bf16_val(h3));
            int base = r * LDP + kq;
            *(uint32_t*)&sAh[base]     = (uint32_t)h0 | ((uint32_t)h1 << 16);
            *(uint32_t*)&sAh[base + 2] = (uint32_t)h2 | ((uint32_t)h3 << 16);
            *(uint32_t*)&sAl[base]     = (uint32_t)l0 | ((uint32_t)l1 << 16);
            *(uint32_t*)&sAl[base + 2] = (uint32_t)l2 | ((uint32_t)l3 << 16);
        }
        {
            const size_t cb = ((size_t)c << 14) + (size_t)col0 * 64;
#pragma unroll
            for (int i = 0; i < 4; i++) {
                int f = tid + i * 256;
                int n = f >> 3, k8 = (f & 7) * 8;
                *(uint4*)&sBh[n * LDP + k8] = *(const uint4*)(Bh + cb + n * 64 + k8);
                *(uint4*)&sBl[n * LDP + k8] = *(const uint4*)(Bl + cb + n * 64 + k8);
            }
        }
        __syncthreads();

#pragma unroll
        for (int ks = 0; ks < 4; ks++) {
            uint32_t ah[2][4], al[2][4];
#pragma unroll
            for (int mi = 0; mi < 2; mi++) {
                int base = (wm * 32 + mi * 16 + g) * LDP + ks * 16 + 2 * t;
                ah[mi][0] = *(const uint32_t*)&sAh[base];
                ah[mi][1] = *(const uint32_t*)&sAh[base + 8 * LDP];
                ah[mi][2] = *(const uint32_t*)&sAh[base + 8];
                ah[mi][3] = *(const uint32_t*)&sAh[base + 8 * LDP + 8];
                al[mi][0] = *(const uint32_t*)&sAl[base];
                al[mi][1] = *(const uint32_t*)&sAl[base + 8 * LDP];
                al[mi][2] = *(const uint32_t*)&sAl[base + 8];
                al[mi][3] = *(const uint32_t*)&sAl[base + 8 * LDP + 8];
            }
#pragma unroll
            for (int ni = 0; ni < 8; ni++) {
                int bb = (wn * 64 + ni * 8 + g) * LDP + ks * 16 + 2 * t;
                uint32_t bh0 = *(const uint32_t*)&sBh[bb];
                uint32_t bh1 = *(const uint32_t*)&sBh[bb + 8];
                uint32_t bl0 = *(const uint32_t*)&sBl[bb];
                uint32_t bl1 = *(const uint32_t*)&sBl[bb + 8];
#pragma unroll
                for (int mi = 0; mi < 2; mi++) {
                    mma16816(acc[mi][ni], ah[mi], bh0, bh1);
                    mma16816(acc[mi][ni], ah[mi], bl0, bl1);
                    mma16816(acc[mi][ni], al[mi], bh0, bh1);
                }
            }
        }
    }

#pragma unroll
    for (int mi = 0; mi < 2; mi++) {
        int r0 = row0 + wm * 32 + mi * 16 + g;
#pragma unroll
        for (int half_ = 0; half_ < 2; half_++) {
            int r = r0 + half_ * 8;
            if (r >= M) continue;
#pragma unroll
            for (int ni = 0; ni < 8; ni++) {
                int cg = col0 + wn * 64 + ni * 8 + 2 * t;
                float v0 = acc[mi][ni][half_ * 2 + 0] + __ldg(&bias[cg]);
                float v1 = acc[mi][ni][half_ * 2 + 1] + __ldg(&bias[cg + 1]);
                v0 = fminf(fmaxf(v0, 0.f), 65504.f);
                v1 = fminf(fmaxf(v1, 0.f), 65504.f);
                __half2 o = __floats2half2_rn(v0, v1);
                *(__half2*)(Ch + (size_t)r * HH + cg) = o;
                *(__half2*)(C2 + (size_t)r * HH + cg) = o;
            }
        }
    }
}

// ---------------------------------------------------------------------------
// FUSED layer: per 128-row tile, gather mix (spmm + x0 residual) into SMEM
// as bf16 hi/lo, then 3-term HMMA GEMM with W' chunks. Writes hnext (fp16).
// 512 threads = 16 warps (4x4 grid, warp tile 32x64). 1 CTA/SM.
// ---------------------------------------------------------------------------
#define FLDA 264                        // A smem pitch (halfs): 132 words -> 4g banks
#define FLDB 72
#define FSM_BH (2 * 128 * FLDA)
#define FSM_BL (FSM_BH + 256 * FLDB)
#define FSM_TOT ((FSM_BL + 256 * FLDB) * 2)   // bytes = 208896

__global__ __launch_bounds__(512, 1)
void fused_layer(const int* __restrict__ rowptr,
                 const int* __restrict__ cols,
                 const float* __restrict__ vals,
                 const __half* __restrict__ hprev,
                 const __half* __restrict__ x0h,
                 const uint16_t* __restrict__ Bh,
                 const uint16_t* __restrict__ Bl,
                 int chunk0, float x0c,
                 __half* __restrict__ hnext, int M)
{
    extern __shared__ uint16_t sm[];
    uint16_t* sMh = sm;                       // [128][FLDA]
    uint16_t* sMl = sm + 128 * FLDA;
    uint16_t* sBh = sm + FSM_BH;              // [256][FLDB]
    uint16_t* sBl = sm + FSM_BL;

    const int tid = threadIdx.x;
    const int warp = tid >> 5, lane = tid & 31;
    const int row0 = blockIdx.x * 128;

    // ---- Phase 1: gather mix rows (fp32 accum), store bf16 hi/lo ----
    for (int rr = warp; rr < 128; rr += 16) {
        int row = row0 + rr;
        float acc[8] = {0.f, 0.f, 0.f, 0.f, 0.f, 0.f, 0.f, 0.f};
        if (row < M) {
            {   // x0 residual (fp16)
                uint4 q = __ldg((const uint4*)(x0h + (size_t)row * HH) + lane);
                float2 f0 = __half22float2(*reinterpret_cast<__half2*>(&q.x));
                float2 f1 = __half22float2(*reinterpret_cast<__half2*>(&q.y));
                float2 f2 = __half22float2(*reinterpret_cast<__half2*>(&q.z));
                float2 f3 = __half22float2(*reinterpret_cast<__half2*>(&q.w));
                acc[0] = x0c * f0.x; acc[1] = x0c * f0.y;
                acc[2] = x0c * f1.x; acc[3] = x0c * f1.y;
                acc[4] = x0c * f2.x; acc[5] = x0c * f2.y;
                acc[6] = x0c * f3.x; acc[7] = x0c * f3.y;
            }
            int s = __ldg(&rowptr[row]);
            int e = __ldg(&rowptr[row + 1]);
            int i = s;
#define GATH(cc, vv) do {                                                  \
        uint4 q = __ldg((const uint4*)(hprev + (size_t)(cc) * HH) + lane); \
        float2 f0 = __half22float2(*reinterpret_cast<__half2*>(&q.x));     \
        float2 f1 = __half22float2(*reinterpret_cast<__half2*>(&q.y));     \
        float2 f2 = __half22float2(*reinterpret_cast<__half2*>(&q.z));     \
        float2 f3 = __half22float2(*reinterpret_cast<__half2*>(&q.w));     \
        acc[0] += (vv) * f0.x; acc[1] += (vv) * f0.y;                      \
        acc[2] += (vv) * f1.x; acc[3] += (vv) * f1.y;                      \
        acc[4] += (vv) * f2.x; acc[5] += (vv) * f2.y;                      \
        acc[6] += (vv) * f3.x; acc[7] += (vv) * f3.y;                      \
    } while (0)
            for (; i + 4 <= e; i += 4) {
                int   c0 = __ldg(&cols[i]),     c1 = __ldg(&cols[i + 1]);
                int   c2 = __ldg(&cols[i + 2]), c3 = __ldg(&cols[i + 3]);
                float v0 = __ldg(&vals[i]),     v1 = __ldg(&vals[i + 1]);
                float v2 = __ldg(&vals[i + 2]), v3 = __ldg(&vals[i + 3]);
                GATH(c0, v0); GATH(c1, v1); GATH(c2, v2); GATH(c3, v3);
            }
            for (; i < e; i++) {
                int c = __ldg(&cols[i]);
                float v = __ldg(&vals[i]);
                GATH(c, v);
            }
#undef GATH
        }
        // split fp32 -> bf16 hi/lo, pack 8 halfs each -> uint4
        uint16_t hi[8], lo[8];
#pragma unroll
        for (int j = 0; j < 8; j++) {
            hi[j] = bf16_bits(acc[j]);
            lo[j] = bf16_bits(acc[j] - bf16_val(hi[j]));
        }
        uint4 ph, pl;
        ph.x = (uint32_t)hi[0] | ((uint32_t)hi[1] << 16);
        ph.y = (uint32_t)hi[2] | ((uint32_t)hi[3] << 16);
        ph.z = (uint32_t)hi[4] | ((uint32_t)hi[5] << 16);
        ph.w = (uint32_t)hi[6] | ((uint32_t)hi[7] << 16);
        pl.x = (uint32_t)lo[0] | ((uint32_t)lo[1] << 16);
        pl.y = (uint32_t)lo[2] | ((uint32_t)lo[3] << 16);
        pl.z = (uint32_t)lo[4] | ((uint32_t)lo[5] << 16);
        pl.w = (uint32_t)lo[6] | ((uint32_t)lo[7] << 16);
        *(uint4*)&sMh[rr * FLDA + lane * 8] = ph;
        *(uint4*)&sMl[rr * FLDA + lane * 8] = pl;
    }
    __syncthreads();

    // ---- Phase 2: GEMM over 4 K-chunks ----
    const int wm = warp >> 2, wn = warp & 3;
    const int g = lane >> 2, t = lane & 3;

    float acc[2][8][4];
#pragma unroll
    for (int mi = 0; mi < 2; mi++)
#pragma unroll
        for (int ni = 0; ni < 8; ni++)
#pragma unroll
            for (int q = 0; q < 4; q++) acc[mi][ni][q] = 0.f;

    for (int c = 0; c < 4; c++) {
        if (c) __syncthreads();
        {   // stage B chunk: 256 n-rows x 64 k
            const size_t cb = ((size_t)(chunk0 + c) << 14);
#pragma unroll
            for (int i = 0; i < 4; i++) {
                int f = tid + i * 512;            // 2048 uint4 per buffer
                int n = f >> 3, k8 = (f & 7) * 8;
                *(uint4*)&sBh[n * FLDB + k8] = *(const uint4*)(Bh + cb + n * 64 + k8);
                *(uint4*)&sBl[n * FLDB + k8] = *(const uint4*)(Bl + cb + n * 64 + k8);
            }
        }
        __syncthreads();

#pragma unroll
        for (int ks = 0; ks < 4; ks++) {
            uint32_t ah[2][4], al[2][4];
#pragma unroll
            for (int mi = 0; mi < 2; mi++) {
                int base = (wm * 32 + mi * 16 + g) * FLDA + c * 64 + ks * 16 + 2 * t;
                ah[mi][0] = *(const uint32_t*)&sMh[base];
                ah[mi][1] = *(const uint32_t*)&sMh[base + 8 * FLDA];
                ah[mi][2] = *(const uint32_t*)&sMh[base + 8];
                ah[mi][3] = *(const uint32_t*)&sMh[base + 8 * FLDA + 8];
                al[mi][0] = *(const uint32_t*)&sMl[base];
                al[mi][1] = *(const uint32_t*)&sMl[base + 8 * FLDA];
                al[mi][2] = *(const uint32_t*)&sMl[base + 8];
                al[mi][3] = *(const uint32_t*)&sMl[base + 8 * FLDA + 8];
            }
#pragma unroll
            for (int ni = 0; ni < 8; ni++) {
                int bb = (wn * 64 + ni * 8 + g) * FLDB + ks * 16 + 2 * t;
                uint32_t bh0 = *(const uint32_t*)&sBh[bb];
                uint32_t bh1 = *(const uint32_t*)&sBh[bb + 8];
                uint32_t bl0 = *(const uint32_t*)&sBl[bb];
                uint32_t bl1 = *(const uint32_t*)&sBl[bb + 8];
#pragma unroll
                for (int mi = 0; mi < 2; mi++) {
                    mma16816(acc[mi][ni], ah[mi], bh0, bh1);
                    mma16816(acc[mi][ni], ah[mi], bl0, bl1);
                    mma16816(acc[mi][ni], al[mi], bh0, bh1);
                }
            }
        }
    }

    // ---- Epilogue: relu + clamp -> hnext fp16 ----
#pragma unroll
    for (int mi = 0; mi < 2; mi++) {
        int r0 = row0 + wm * 32 + mi * 16 + g;
#pragma unroll
        for (int half_ = 0; half_ < 2; half_++) {
            int r = r0 + half_ * 8;
            if (r >= M) continue;
#pragma unroll
            for (int ni = 0; ni < 8; ni++) {
                int cg = wn * 64 + ni * 8 + 2 * t;
                float v0 = fminf(fmaxf(acc[mi][ni][half_ * 2 + 0], 0.f), 65504.f);
                float v1 = fminf(fmaxf(acc[mi][ni][half_ * 2 + 1], 0.f), 65504.f);
                *(__half2*)(hnext + (size_t)r * HH + cg) = __floats2half2_rn(v0, v1);
            }
        }
    }
}

// ---------------------------------------------------------------------------
// CSR build
// ---------------------------------------------------------------------------
__global__ void hist_kernel(const int* __restrict__ erow, int* __restrict__ cnt, int E)
{
    for (int e = blockIdx.x * blockDim.x + threadIdx.x; e < E;
         e += gridDim.x * blockDim.x)
        atomicAdd(&cnt[__ldg(&erow[e])], 1);
}

__global__ __launch_bounds__(1024)
void scan_kernel(const int* __restrict__ cnt, int* __restrict__ rowptr)
{
    __shared__ int warpsums[32];
    __shared__ int running;
    int tid = threadIdx.x, lane = tid & 31, wid = tid >> 5;
    if (tid == 0) running = 0;
    __syncthreads();
    for (int base = 0; base < NN; base += 1024) {
        int v = (base + tid < NN) ? cnt[base + tid] : 0;
        int x = v;
#pragma unroll
        for (int o = 1; o < 32; o <<= 1) {
            int t = __shfl_up_sync(0xffffffffu, x, o);
            if (lane >= o) x += t;
        }
        if (lane == 31) warpsums[wid] = x;
        __syncthreads();
        if (wid == 0) {
            int s = warpsums[lane];
#pragma unroll
            for (int o = 1; o < 32; o <<= 1) {
                int t = __shfl_up_sync(0xffffffffu, s, o);
                if (lane >= o) s += t;
            }
            warpsums[lane] = s;
        }
        __syncthreads();
        int incl = x + (wid > 0 ? warpsums[wid - 1] : 0) + running;
        if (base + tid < NN) rowptr[base + tid + 1] = incl;
        __syncthreads();
        if (tid == 1023) running = incl;
        __syncthreads();
    }
    if (tid == 0) rowptr[0] = 0;
}

__global__ void scatter_kernel(const int* __restrict__ erow,
                               const int* __restrict__ ecol,
                               const float* __restrict__ eval,
                               const int* __restrict__ rowptr,
                               int* __restrict__ cnt,
                               int* __restrict__ csr_col,
                               float* __restrict__ csr_val, int E)
{
    for (int e = blockIdx.x * blockDim.x + threadIdx.x; e < E;
         e += gridDim.x * blockDim.x) {
        int r = __ldg(&erow[e]);
        int p = __ldg(&rowptr[r]) + atomicAdd(&cnt[r], 1);
        csr_col[p] = __ldg(&ecol[e]);
        csr_val[p] = __ldg(&eval[e]) * ((1.0f - ALPHA) * SCL);
    }
}

// ---------------------------------------------------------------------------
// Output head: logits = UNSCALE*(h_scaled @ W_out) + b, then log_softmax.
// ---------------------------------------------------------------------------
__global__ __launch_bounds__(256)
void out_kernel(const __half* __restrict__ h, const float* __restrict__ W,
                const float* __restrict__ b, float* __restrict__ out, int M)
{
    __shared__ float hs[8][HH];
    int tid = threadIdx.x;
    int warp = tid >> 5, lane = tid & 31;
    int row = blockIdx.x * 8 + warp;

    if (row < M) {
        const uint4* hp = (const uint4*)(h + (size_t)row * HH);
        uint4 q = __ldg(&hp[lane]);
        float2 f0 = __half22float2(*reinterpret_cast<__half2*>(&q.x));
        float2 f1 = __half22float2(*reinterpret_cast<__half2*>(&q.y));
        float2 f2 = __half22float2(*reinterpret_cast<__half2*>(&q.z));
        float2 f3 = __half22float2(*reinterpret_cast<__half2*>(&q.w));
        int base = lane * 8;
        hs[warp][base + 0] = f0.x; hs[warp][base + 1] = f0.y;
        hs[warp][base + 2] = f1.x; hs[warp][base + 3] = f1.y;
        hs[warp][base + 4] = f2.x; hs[warp][base + 5] = f2.y;
        hs[warp][base + 6] = f3.x; hs[warp][base + 7] = f3.y;
    }
    __syncthreads();
    if (row >= M) return;

    float l0 = 0.f, l1 = 0.f;
#pragma unroll 8
    for (int k = 0; k < HH; k++) {
        float hv = hs[warp][k];
        l0 += hv * __ldg(&W[k * CC + lane]);
        l1 += hv * __ldg(&W[k * CC + lane + 32]);
    }
    l0 = l0 * UNSCALE + __ldg(&b[lane]);
    l1 = l1 * UNSCALE + __ldg(&b[lane + 32]);
    float m = fmaxf(l0, l1);
#pragma unroll
    for (int o = 16; o; o >>= 1) m = fmaxf(m, __shfl_xor_sync(0xffffffffu, m, o));
    float s = expf(l0 - m) + expf(l1 - m);
#pragma unroll
    for (int o = 16; o; o >>= 1) s += __shfl_xor_sync(0xffffffffu, s, o);
    float lse = m + logf(s);
    out[(size_t)row * CC + lane] = l0 - lse;
    out[(size_t)row * CC + lane + 32] = l1 - lse;
}

// ---------------------------------------------------------------------------
extern "C" void kernel_launch(void* const* d_in, const int* in_sizes, int n_in,
                              void* d_out, int out_size)
{
    const float* x        = (const float*)d_in[0];
    const float* edge_val = (const float*)d_in[1];
    const float* W_in     = (const float*)d_in[2];
    const float* b_in     = (const float*)d_in[3];
    const float* conv_W   = (const float*)d_in[4];
    const float* W_out    = (const float*)d_in[5];
    const float* b_out    = (const float*)d_in[6];
    const int*   erow     = (const int*)d_in[7];
    const int*   ecol     = (const int*)d_in[8];
    float* out = (float*)d_out;

    __half *hhA, *hhB, *x0h;
    float *csr_val;
    int *rowptr, *cnt, *csr_col;
    uint16_t *Bh, *Bl;
    cudaGetSymbolAddress((void**)&hhA,     g_hhA);
    cudaGetSymbolAddress((void**)&hhB,     g_hhB);
    cudaGetSymbolAddress((void**)&x0h,     g_x0h);
    cudaGetSymbolAddress((void**)&rowptr,  g_rowptr);
    cudaGetSymbolAddress((void**)&cnt,     g_cnt);
    cudaGetSymbolAddress((void**)&csr_col, g_col);
    cudaGetSymbolAddress((void**)&csr_val, g_val);
    cudaGetSymbolAddress((void**)&Bh,      g_Bh);
    cudaGetSymbolAddress((void**)&Bl,      g_Bl);

    const int smem_in = 4 * SA_ELEMS * sizeof(uint16_t);      // 73728
    cudaFuncSetAttribute(mma_gemm_in,
                         cudaFuncAttributeMaxDynamicSharedMemorySize, smem_in);
    cudaFuncSetAttribute(fused_layer,
                         cudaFuncAttributeMaxDynamicSharedMemorySize, FSM_TOT);

    // ---- B library + CSR build ----
    prep_B_kernel<<<(NCHUNKS_TOT * CHUNK_ELEMS + 255) / 256, 256>>>(
        W_in, conv_W, Bh, Bl);
    cudaMemsetAsync(cnt, 0, NN * sizeof(int));
    hist_kernel<<<592, 256>>>(erow, cnt, EE);
    scan_kernel<<<1, 1024>>>(cnt, rowptr);
    cudaMemsetAsync(cnt, 0, NN * sizeof(int));
    scatter_kernel<<<592, 256>>>(erow, ecol, edge_val, rowptr, cnt,
                                 csr_col, csr_val, EE);

    // ---- h0 = relu(x @ W_in + b_in) -> hhA (fp16), x0h (fp16) ----
    {
        dim3 grid(2, (NN + 127) / 128);
        mma_gemm_in<<<grid, 256, smem_in>>>(x, Bh, Bl, b_in, hhA, x0h, NN);
    }

    __half* hprev = hhA;
    __half* hnext = hhB;
    const int fgrid = (NN + 127) / 128;   // 782
    for (int l = 0; l < LL; l++) {
        float x0c = ALPHA * ldexpf(1.0f, -4 * (l + 1));   // alpha * s^{l+1}
        fused_layer<<<fgrid, 512, FSM_TOT>>>(rowptr, csr_col, csr_val,
                                             hprev, x0h, Bh, Bl,
                                             8 + 4 * l, x0c, hnext, NN);
        __half* tmp = hprev; hprev = hnext; hnext = tmp;
    }

    out_kernel<<<(NN + 7) / 8, 256>>>(hprev, W_out, b_out, out, NN);
}

// round 16
// speedup vs baseline: 1.4438x; 1.4438x over previous
#include <cuda_runtime.h>
#include <cuda_bf16.h>
#include <cuda_fp16.h>
#include <math.h>
#include <stdint.h>

#define NN 100000
#define EE 3200000
#define FIN 512
#define HH 256
#define CC 64
#define LL 8
#define ALPHA 0.1f
#define SCL 0.0625f                     // per-layer storage scale s = 1/16
#define UNSCALE 4294967296.0f           // s^-8 = 2^32 (exact fp32)

#define NCHUNKS_TOT 40
#define CHUNK_ELEMS 16384

// ---------------- scratch (no cudaMalloc allowed) ----------------
__device__ __align__(16) __half g_hh[(size_t)NN * HH];    // scaled h, fp16
__device__ __align__(16) __half g_x0h[(size_t)NN * HH];   // x0, fp16
__device__ __align__(16) __half g_mixh[(size_t)NN * HH];  // scaled mix, fp16
__device__ int    g_rowptr[NN + 1];
__device__ int    g_cnt[NN];
__device__ int    g_col[EE];
__device__ float  g_val[EE];
__device__ __align__(16) uint16_t g_Bh[(size_t)NCHUNKS_TOT * CHUNK_ELEMS];
__device__ __align__(16) uint16_t g_Bl[(size_t)NCHUNKS_TOT * CHUNK_ELEMS];

// ---------------------------------------------------------------------------
__device__ __forceinline__ uint16_t bf16_bits(float v) {
    __nv_bfloat16 b = __float2bfloat16_rn(v);
    return *reinterpret_cast<uint16_t*>(&b);
}
__device__ __forceinline__ float bf16_val(uint16_t u) {
    __nv_bfloat16 b = *reinterpret_cast<__nv_bfloat16*>(&u);
    return __bfloat162float(b);
}

__device__ __forceinline__ void mma16816(float* d, const uint32_t* a,
                                         uint32_t b0, uint32_t b1) {
    asm volatile(
        "mma.sync.aligned.m16n8k16.row.col.f32.bf16.bf16.f32 "
        "{%0,%1,%2,%3}, {%4,%5,%6,%7}, {%8,%9}, {%0,%1,%2,%3};"
        : "+f"(d[0]), "+f"(d[1]), "+f"(d[2]), "+f"(d[3])
        : "r"(a[0]), "r"(a[1]), "r"(a[2]), "r"(a[3]), "r"(b0), "r"(b1));
}

// ---------------------------------------------------------------------------
// B chunk library: chunks 0..7 = W_in (K=512); 8+4l+c = beta*W_l + (1-beta)I.
// ---------------------------------------------------------------------------
__global__ void prep_B_kernel(const float* __restrict__ Win,
                              const float* __restrict__ convW,
                              uint16_t* __restrict__ Bh, uint16_t* __restrict__ Bl)
{
    int e = blockIdx.x * 256 + threadIdx.x;
    if (e >= NCHUNKS_TOT * CHUNK_ELEMS) return;
    int chunk = e >> 14, w = e & 16383;
    int n = w >> 6, kk = w & 63;
    float val;
    if (chunk < 8) {
        val = __ldg(&Win[(chunk * 64 + kk) * HH + n]);
    } else {
        int l = (chunk - 8) >> 2, c = (chunk - 8) & 3, k = c * 64 + kk;
        float beta = logf(0.5f / (float)(l + 1) + 1.0f);
        val = beta * __ldg(&convW[(size_t)l * HH * HH + (size_t)k * HH + n]);
        if (k == n) val += 1.0f - beta;
    }
    uint16_t hi = bf16_bits(val);
    uint16_t lo = bf16_bits(val - bf16_val(hi));
    Bh[e] = hi;
    Bl[e] = lo;
}

// ---------------------------------------------------------------------------
// Shared GEMM guts: 256 threads, BM=BN=128, BK=64, 8 warps (4x2), 3-term split.
// A staged in sAh/sAl by the caller-specific loader below.
// ---------------------------------------------------------------------------
#define LDP 72
#define SA_ELEMS (128 * LDP)

// Input GEMM: A fp32 [M,512]; writes Ch (h fp16) + C2 (x0 fp16).
__global__ __launch_bounds__(256, 2)
void mma_gemm_in(const float* __restrict__ A,
                 const uint16_t* __restrict__ Bh, const uint16_t* __restrict__ Bl,
                 const float* __restrict__ bias,
                 __half* __restrict__ Ch, __half* __restrict__ C2, int M)
{
    extern __shared__ uint16_t sm[];
    uint16_t* sAh = sm;
    uint16_t* sAl = sm + SA_ELEMS;
    uint16_t* sBh = sm + 2 * SA_ELEMS;
    uint16_t* sBl = sm + 3 * SA_ELEMS;

    const int tid = threadIdx.x;
    const int warp = tid >> 5, lane = tid & 31;
    const int wm = warp >> 1, wn = warp & 1;
    const int g = lane >> 2, t = lane & 3;
    const int row0 = blockIdx.y * 128;
    const int col0 = blockIdx.x * 128;

    float acc[2][8][4];
#pragma unroll
    for (int mi = 0; mi < 2; mi++)
#pragma unroll
        for (int ni = 0; ni < 8; ni++)
#pragma unroll
            for (int q = 0; q < 4; q++) acc[mi][ni][q] = 0.f;

    for (int c = 0; c < 8; c++) {
        __syncthreads();
#pragma unroll
        for (int i = 0; i < 8; i++) {
            int f = tid + i * 256;
            int r = f >> 4, kq = (f & 15) * 4;
            float4 v = make_float4(0.f, 0.f, 0.f, 0.f);
            if (row0 + r < M)
                v = *(const float4*)(A + (size_t)(row0 + r) * FIN + c * 64 + kq);
            uint16_t h0 = bf16_bits(v.x), h1 = bf16_bits(v.y);
            uint16_t h2 = bf16_bits(v.z), h3 = bf16_bits(v.w);
            uint16_t l0 = bf16_bits(v.x - bf16_val(h0));
            uint16_t l1 = bf16_bits(v.y - bf16_val(h1));
            uint16_t l2 = bf16_bits(v.z - bf16_val(h2));
            uint16_t l3 = bf16_bits(v.w - bf16_val(h3));
            int base = r * LDP + kq;
            *(uint32_t*)&sAh[base]     = (uint32_t)h0 | ((uint32_t)h1 << 16);
            *(uint32_t*)&sAh[base + 2] = (uint32_t)h2 | ((uint32_t)h3 << 16);
            *(uint32_t*)&sAl[base]     = (uint32_t)l0 | ((uint32_t)l1 << 16);
            *(uint32_t*)&sAl[base + 2] = (uint32_t)l2 | ((uint32_t)l3 << 16);
        }
        {
            const size_t cb = ((size_t)c << 14) + (size_t)col0 * 64;
#pragma unroll
            for (int i = 0; i < 4; i++) {
                int f = tid + i * 256;
                int n = f >> 3, k8 = (f & 7) * 8;
                *(uint4*)&sBh[n * LDP + k8] = *(const uint4*)(Bh + cb + n * 64 + k8);
                *(uint4*)&sBl[n * LDP + k8] = *(const uint4*)(Bl + cb + n * 64 + k8);
            }
        }
        __syncthreads();

#pragma unroll
        for (int ks = 0; ks < 4; ks++) {
            uint32_t ah[2][4], al[2][4];
#pragma unroll
            for (int mi = 0; mi < 2; mi++) {
                int base = (wm * 32 + mi * 16 + g) * LDP + ks * 16 + 2 * t;
                ah[mi][0] = *(const uint32_t*)&sAh[base];
                ah[mi][1] = *(const uint32_t*)&sAh[base + 8 * LDP];
                ah[mi][2] = *(const uint32_t*)&sAh[base + 8];
                ah[mi][3] = *(const uint32_t*)&sAh[base + 8 * LDP + 8];
                al[mi][0] = *(const uint32_t*)&sAl[base];
                al[mi][1] = *(const uint32_t*)&sAl[base + 8 * LDP];
                al[mi][2] = *(const uint32_t*)&sAl[base + 8];
                al[mi][3] = *(const uint32_t*)&sAl[base + 8 * LDP + 8];
            }
#pragma unroll
            for (int ni = 0; ni < 8; ni++) {
                int bb = (wn * 64 + ni * 8 + g) * LDP + ks * 16 + 2 * t;
                uint32_t bh0 = *(const uint32_t*)&sBh[bb];
                uint32_t bh1 = *(const uint32_t*)&sBh[bb + 8];
                uint32_t bl0 = *(const uint32_t*)&sBl[bb];
                uint32_t bl1 = *(const uint32_t*)&sBl[bb + 8];
#pragma unroll
                for (int mi = 0; mi < 2; mi++) {
                    mma16816(acc[mi][ni], ah[mi], bh0, bh1);
                    mma16816(acc[mi][ni], ah[mi], bl0, bl1);
                    mma16816(acc[mi][ni], al[mi], bh0, bh1);
                }
            }
        }
    }

#pragma unroll
    for (int mi = 0; mi < 2; mi++) {
        int r0 = row0 + wm * 32 + mi * 16 + g;
#pragma unroll
        for (int half_ = 0; half_ < 2; half_++) {
            int r = r0 + half_ * 8;
            if (r >= M) continue;
#pragma unroll
            for (int ni = 0; ni < 8; ni++) {
                int cg = col0 + wn * 64 + ni * 8 + 2 * t;
                float v0 = acc[mi][ni][half_ * 2 + 0] + __ldg(&bias[cg]);
                float v1 = acc[mi][ni][half_ * 2 + 1] + __ldg(&bias[cg + 1]);
                v0 = fminf(fmaxf(v0, 0.f), 65504.f);
                v1 = fminf(fmaxf(v1, 0.f), 65504.f);
                __half2 o = __floats2half2_rn(v0, v1);
                *(__half2*)(Ch + (size_t)r * HH + cg) = o;
                *(__half2*)(C2 + (size_t)r * HH + cg) = o;
            }
        }
    }
}

// Layer GEMM: A fp16 [M,256] (mix); writes Ch = relu(A@B') fp16.
__global__ __launch_bounds__(256, 2)
void mma_gemm_h(const __half* __restrict__ A,
                const uint16_t* __restrict__ Bh, const uint16_t* __restrict__ Bl,
                int chunk0,
                __half* __restrict__ Ch, int M)
{
    extern __shared__ uint16_t sm[];
    uint16_t* sAh = sm;
    uint16_t* sAl = sm + SA_ELEMS;
    uint16_t* sBh = sm + 2 * SA_ELEMS;
    uint16_t* sBl = sm + 3 * SA_ELEMS;

    const int tid = threadIdx.x;
    const int warp = tid >> 5, lane = tid & 31;
    const int wm = warp >> 1, wn = warp & 1;
    const int g = lane >> 2, t = lane & 3;
    const int row0 = blockIdx.y * 128;
    const int col0 = blockIdx.x * 128;

    float acc[2][8][4];
#pragma unroll
    for (int mi = 0; mi < 2; mi++)
#pragma unroll
        for (int ni = 0; ni < 8; ni++)
#pragma unroll
            for (int q = 0; q < 4; q++) acc[mi][ni][q] = 0.f;

    for (int c = 0; c < 4; c++) {
        __syncthreads();
        // A chunk: 128 rows x 64 k fp16 -> split bf16 hi/lo. 1024 uint4 loads.
#pragma unroll
        for (int i = 0; i < 4; i++) {
            int f = tid + i * 256;
            int r = f >> 3, k8 = (f & 7) * 8;
            uint4 q = make_uint4(0, 0, 0, 0);
            if (row0 + r < M)
                q = *(const uint4*)(A + (size_t)(row0 + r) * HH + c * 64 + k8);
            uint16_t hi[8], lo[8];
            const __half* hp = reinterpret_cast<const __half*>(&q);
#pragma unroll
            for (int j = 0; j < 8; j++) {
                float v = __half2float(hp[j]);
                hi[j] = bf16_bits(v);
                lo[j] = bf16_bits(v - bf16_val(hi[j]));
            }
            int base = r * LDP + k8;
            *(uint32_t*)&sAh[base]     = (uint32_t)hi[0] | ((uint32_t)hi[1] << 16);
            *(uint32_t*)&sAh[base + 2] = (uint32_t)hi[2] | ((uint32_t)hi[3] << 16);
            *(uint32_t*)&sAh[base + 4] = (uint32_t)hi[4] | ((uint32_t)hi[5] << 16);
            *(uint32_t*)&sAh[base + 6] = (uint32_t)hi[6] | ((uint32_t)hi[7] << 16);
            *(uint32_t*)&sAl[base]     = (uint32_t)lo[0] | ((uint32_t)lo[1] << 16);
            *(uint32_t*)&sAl[base + 2] = (uint32_t)lo[2] | ((uint32_t)lo[3] << 16);
            *(uint32_t*)&sAl[base + 4] = (uint32_t)lo[4] | ((uint32_t)lo[5] << 16);
            *(uint32_t*)&sAl[base + 6] = (uint32_t)lo[6] | ((uint32_t)lo[7] << 16);
        }
        {
            const size_t cb = ((size_t)(chunk0 + c) << 14) + (size_t)col0 * 64;
#pragma unroll
            for (int i = 0; i < 4; i++) {
                int f = tid + i * 256;
                int n = f >> 3, k8 = (f & 7) * 8;
                *(uint4*)&sBh[n * LDP + k8] = *(const uint4*)(Bh + cb + n * 64 + k8);
                *(uint4*)&sBl[n * LDP + k8] = *(const uint4*)(Bl + cb + n * 64 + k8);
            }
        }
        __syncthreads();

#pragma unroll
        for (int ks = 0; ks < 4; ks++) {
            uint32_t ah[2][4], al[2][4];
#pragma unroll
            for (int mi = 0; mi < 2; mi++) {
                int base = (wm * 32 + mi * 16 + g) * LDP + ks * 16 + 2 * t;
                ah[mi][0] = *(const uint32_t*)&sAh[base];
                ah[mi][1] = *(const uint32_t*)&sAh[base + 8 * LDP];
                ah[mi][2] = *(const uint32_t*)&sAh[base + 8];
                ah[mi][3] = *(const uint32_t*)&sAh[base + 8 * LDP + 8];
                al[mi][0] = *(const uint32_t*)&sAl[base];
                al[mi][1] = *(const uint32_t*)&sAl[base + 8 * LDP];
                al[mi][2] = *(const uint32_t*)&sAl[base + 8];
                al[mi][3] = *(const uint32_t*)&sAl[base + 8 * LDP + 8];
            }
#pragma unroll
            for (int ni = 0; ni < 8; ni++) {
                int bb = (wn * 64 + ni * 8 + g) * LDP + ks * 16 + 2 * t;
                uint32_t bh0 = *(const uint32_t*)&sBh[bb];
                uint32_t bh1 = *(const uint32_t*)&sBh[bb + 8];
                uint32_t bl0 = *(const uint32_t*)&sBl[bb];
                uint32_t bl1 = *(const uint32_t*)&sBl[bb + 8];
#pragma unroll
                for (int mi = 0; mi < 2; mi++) {
                    mma16816(acc[mi][ni], ah[mi], bh0, bh1);
                    mma16816(acc[mi][ni], ah[mi], bl0, bl1);
                    mma16816(acc[mi][ni], al[mi], bh0, bh1);
                }
            }
        }
    }

#pragma unroll
    for (int mi = 0; mi < 2; mi++) {
        int r0 = row0 + wm * 32 + mi * 16 + g;
#pragma unroll
        for (int half_ = 0; half_ < 2; half_++) {
            int r = r0 + half_ * 8;
            if (r >= M) continue;
#pragma unroll
            for (int ni = 0; ni < 8; ni++) {
                int cg = col0 + wn * 64 + ni * 8 + 2 * t;
                float v0 = fminf(fmaxf(acc[mi][ni][half_ * 2 + 0], 0.f), 65504.f);
                float v1 = fminf(fmaxf(acc[mi][ni][half_ * 2 + 1], 0.f), 65504.f);
                *(__half2*)(Ch + (size_t)r * HH + cg) = __floats2half2_rn(v0, v1);
            }
        }
    }
}

// ---------------------------------------------------------------------------
// CSR build
// ---------------------------------------------------------------------------
__global__ void hist_kernel(const int* __restrict__ erow, int* __restrict__ cnt, int E)
{
    for (int e = blockIdx.x * blockDim.x + threadIdx.x; e < E;
         e += gridDim.x * blockDim.x)
        atomicAdd(&cnt[__ldg(&erow[e])], 1);
}

__global__ __launch_bounds__(1024)
void scan_kernel(const int* __restrict__ cnt, int* __restrict__ rowptr)
{
    __shared__ int warpsums[32];
    __shared__ int running;
    int tid = threadIdx.x, lane = tid & 31, wid = tid >> 5;
    if (tid == 0) running = 0;
    __syncthreads();
    for (int base = 0; base < NN; base += 1024) {
        int v = (base + tid < NN) ? cnt[base + tid] : 0;
        int x = v;
#pragma unroll
        for (int o = 1; o < 32; o <<= 1) {
            int t = __shfl_up_sync(0xffffffffu, x, o);
            if (lane >= o) x += t;
        }
        if (lane == 31) warpsums[wid] = x;
        __syncthreads();
        if (wid == 0) {
            int s = warpsums[lane];
#pragma unroll
            for (int o = 1; o < 32; o <<= 1) {
                int t = __shfl_up_sync(0xffffffffu, s, o);
                if (lane >= o) s += t;
            }
            warpsums[lane] = s;
        }
        __syncthreads();
        int incl = x + (wid > 0 ? warpsums[wid - 1] : 0) + running;
        if (base + tid < NN) rowptr[base + tid + 1] = incl;
        __syncthreads();
        if (tid == 1023) running = incl;
        __syncthreads();
    }
    if (tid == 0) rowptr[0] = 0;
}

__global__ void scatter_kernel(const int* __restrict__ erow,
                               const int* __restrict__ ecol,
                               const float* __restrict__ eval,
                               const int* __restrict__ rowptr,
                               int* __restrict__ cnt,
                               int* __restrict__ csr_col,
                               float* __restrict__ csr_val, int E)
{
    for (int e = blockIdx.x * blockDim.x + threadIdx.x; e < E;
         e += gridDim.x * blockDim.x) {
        int r = __ldg(&erow[e]);
        int p = __ldg(&rowptr[r]) + atomicAdd(&cnt[r], 1);
        csr_col[p] = __ldg(&ecol[e]);
        csr_val[p] = __ldg(&eval[e]) * ((1.0f - ALPHA) * SCL);
    }
}

// ---------------------------------------------------------------------------
// CSR SpMM: fp16 gather + fp16 x0, fp32 accum, fp16 mix out. Warp per row.
// ---------------------------------------------------------------------------
__global__ __launch_bounds__(256)
void spmm_half_kernel(const int* __restrict__ rowptr,
                      const int* __restrict__ cols,
                      const float* __restrict__ vals,
                      const __half* __restrict__ h,
                      const __half* __restrict__ x0h,
                      __half* __restrict__ mix, float x0c, int M)
{
    int row = (blockIdx.x * 256 + threadIdx.x) >> 5;
    int lane = threadIdx.x & 31;
    if (row >= M) return;

    int s = __ldg(&rowptr[row]);
    int e = __ldg(&rowptr[row + 1]);

    float acc[8];
    {
        uint4 q = __ldg((const uint4*)(x0h + (size_t)row * HH) + lane);
        float2 f0 = __half22float2(*reinterpret_cast<__half2*>(&q.x));
        float2 f1 = __half22float2(*reinterpret_cast<__half2*>(&q.y));
        float2 f2 = __half22float2(*reinterpret_cast<__half2*>(&q.z));
        float2 f3 = __half22float2(*reinterpret_cast<__half2*>(&q.w));
        acc[0] = x0c * f0.x; acc[1] = x0c * f0.y;
        acc[2] = x0c * f1.x; acc[3] = x0c * f1.y;
        acc[4] = x0c * f2.x; acc[5] = x0c * f2.y;
        acc[6] = x0c * f3.x; acc[7] = x0c * f3.y;
    }

    int i = s;
#define GATH(cc, vv) do {                                                  \
        uint4 q = __ldg((const uint4*)(h + (size_t)(cc) * HH) + lane);     \
        float2 f0 = __half22float2(*reinterpret_cast<__half2*>(&q.x));     \
        float2 f1 = __half22float2(*reinterpret_cast<__half2*>(&q.y));     \
        float2 f2 = __half22float2(*reinterpret_cast<__half2*>(&q.z));     \
        float2 f3 = __half22float2(*reinterpret_cast<__half2*>(&q.w));     \
        acc[0] += (vv) * f0.x; acc[1] += (vv) * f0.y;                      \
        acc[2] += (vv) * f1.x; acc[3] += (vv) * f1.y;                      \
        acc[4] += (vv) * f2.x; acc[5] += (vv) * f2.y;                      \
        acc[6] += (vv) * f3.x; acc[7] += (vv) * f3.y;                      \
    } while (0)

    for (; i + 4 <= e; i += 4) {
        int   c0 = __ldg(&cols[i]),     c1 = __ldg(&cols[i + 1]);
        int   c2 = __ldg(&cols[i + 2]), c3 = __ldg(&cols[i + 3]);
        float v0 = __ldg(&vals[i]),     v1 = __ldg(&vals[i + 1]);
        float v2 = __ldg(&vals[i + 2]), v3 = __ldg(&vals[i + 3]);
        GATH(c0, v0); GATH(c1, v1); GATH(c2, v2); GATH(c3, v3);
    }
    for (; i < e; i++) {
        int c = __ldg(&cols[i]);
        float v = __ldg(&vals[i]);
        GATH(c, v);
    }
#undef GATH

    // mix out as fp16 (clamped to finite range; mix can be negative)
    uint4 o;
    __half2* op = reinterpret_cast<__half2*>(&o);
#pragma unroll
    for (int j = 0; j < 4; j++) {
        float a0 = fminf(fmaxf(acc[2 * j + 0], -65504.f), 65504.f);
        float a1 = fminf(fmaxf(acc[2 * j + 1], -65504.f), 65504.f);
        op[j] = __floats2half2_rn(a0, a1);
    }
    *((uint4*)(mix + (size_t)row * HH) + lane) = o;
}

// ---------------------------------------------------------------------------
// Output head: logits = UNSCALE*(h_scaled @ W_out) + b, then log_softmax.
// ---------------------------------------------------------------------------
__global__ __launch_bounds__(256)
void out_kernel(const __half* __restrict__ h, const float* __restrict__ W,
                const float* __restrict__ b, float* __restrict__ out, int M)
{
    __shared__ float hs[8][HH];
    int tid = threadIdx.x;
    int warp = tid >> 5, lane = tid & 31;
    int row = blockIdx.x * 8 + warp;

    if (row < M) {
        const uint4* hp = (const uint4*)(h + (size_t)row * HH);
        uint4 q = __ldg(&hp[lane]);
        float2 f0 = __half22float2(*reinterpret_cast<__half2*>(&q.x));
        float2 f1 = __half22float2(*reinterpret_cast<__half2*>(&q.y));
        float2 f2 = __half22float2(*reinterpret_cast<__half2*>(&q.z));
        float2 f3 = __half22float2(*reinterpret_cast<__half2*>(&q.w));
        int base = lane * 8;
        hs[warp][base + 0] = f0.x; hs[warp][base + 1] = f0.y;
        hs[warp][base + 2] = f1.x; hs[warp][base + 3] = f1.y;
        hs[warp][base + 4] = f2.x; hs[warp][base + 5] = f2.y;
        hs[warp][base + 6] = f3.x; hs[warp][base + 7] = f3.y;
    }
    __syncthreads();
    if (row >= M) return;

    float l0 = 0.f, l1 = 0.f;
#pragma unroll 8
    for (int k = 0; k < HH; k++) {
        float hv = hs[warp][k];
        l0 += hv * __ldg(&W[k * CC + lane]);
        l1 += hv * __ldg(&W[k * CC + lane + 32]);
    }
    l0 = l0 * UNSCALE + __ldg(&b[lane]);
    l1 = l1 * UNSCALE + __ldg(&b[lane + 32]);
    float m = fmaxf(l0, l1);
#pragma unroll
    for (int o = 16; o; o >>= 1) m = fmaxf(m, __shfl_xor_sync(0xffffffffu, m, o));
    float s = expf(l0 - m) + expf(l1 - m);
#pragma unroll
    for (int o = 16; o; o >>= 1) s += __shfl_xor_sync(0xffffffffu, s, o);
    float lse = m + logf(s);
    out[(size_t)row * CC + lane] = l0 - lse;
    out[(size_t)row * CC + lane + 32] = l1 - lse;
}

// ---------------------------------------------------------------------------
extern "C" void kernel_launch(void* const* d_in, const int* in_sizes, int n_in,
                              void* d_out, int out_size)
{
    const float* x        = (const float*)d_in[0];
    const float* edge_val = (const float*)d_in[1];
    const float* W_in     = (const float*)d_in[2];
    const float* b_in     = (const float*)d_in[3];
    const float* conv_W   = (const float*)d_in[4];
    const float* W_out    = (const float*)d_in[5];
    const float* b_out    = (const float*)d_in[6];
    const int*   erow     = (const int*)d_in[7];
    const int*   ecol     = (const int*)d_in[8];
    float* out = (float*)d_out;

    __half *hh, *x0h, *mixh;
    float *csr_val;
    int *rowptr, *cnt, *csr_col;
    uint16_t *Bh, *Bl;
    cudaGetSymbolAddress((void**)&hh,      g_hh);
    cudaGetSymbolAddress((void**)&x0h,     g_x0h);
    cudaGetSymbolAddress((void**)&mixh,    g_mixh);
    cudaGetSymbolAddress((void**)&rowptr,  g_rowptr);
    cudaGetSymbolAddress((void**)&cnt,     g_cnt);
    cudaGetSymbolAddress((void**)&csr_col, g_col);
    cudaGetSymbolAddress((void**)&csr_val, g_val);
    cudaGetSymbolAddress((void**)&Bh,      g_Bh);
    cudaGetSymbolAddress((void**)&Bl,      g_Bl);

    const int smem_bytes = 4 * SA_ELEMS * sizeof(uint16_t);   // 73728
    cudaFuncSetAttribute(mma_gemm_in,
                         cudaFuncAttributeMaxDynamicSharedMemorySize, smem_bytes);
    cudaFuncSetAttribute(mma_gemm_h,
                         cudaFuncAttributeMaxDynamicSharedMemorySize, smem_bytes);

    dim3 gemm_grid(2, (NN + 127) / 128);   // (2, 782)

    // ---- B library + CSR build (per replay, deterministic) ----
    prep_B_kernel<<<(NCHUNKS_TOT * CHUNK_ELEMS + 255) / 256, 256>>>(
        W_in, conv_W, Bh, Bl);
    cudaMemsetAsync(cnt, 0, NN * sizeof(int));
    hist_kernel<<<592, 256>>>(erow, cnt, EE);
    scan_kernel<<<1, 1024>>>(cnt, rowptr);
    cudaMemsetAsync(cnt, 0, NN * sizeof(int));
    scatter_kernel<<<592, 256>>>(erow, ecol, edge_val, rowptr, cnt,
                                 csr_col, csr_val, EE);

    // ---- h0 = relu(x @ W_in + b_in) -> hh (fp16), x0h (fp16) ----
    mma_gemm_in<<<gemm_grid, 256, smem_bytes>>>(x, Bh, Bl, b_in, hh, x0h, NN);

    for (int l = 0; l < LL; l++) {
        float x0c = ALPHA * ldexpf(1.0f, -4 * (l + 1));   // alpha * s^{l+1}
        // mix(fp16) = x0c*x0 + (0.9*s)*A @ h
        spmm_half_kernel<<<(NN * 32 + 255) / 256, 256>>>(rowptr, csr_col,
                                                         csr_val, hh, x0h,
                                                         mixh, x0c, NN);
        // h(fp16) = relu( mix @ ((1-beta)I + beta*W_l) )
        mma_gemm_h<<<gemm_grid, 256, smem_bytes>>>(mixh, Bh, Bl, 8 + 4 * l,
                                                   hh, NN);
    }

    out_kernel<<<(NN + 7) / 8, 256>>>(hh, W_out, b_out, out, NN);
}

// round 17
// speedup vs baseline: 1.6047x; 1.1114x over previous
#include <cuda_runtime.h>
#include <cuda_fp16.h>
#include <math.h>
#include <stdint.h>

#define NN 100000
#define EE 3200000
#define FIN 512
#define HH 256
#define CC 64
#define LL 8
#define ALPHA 0.1f
#define SCL 0.0625f                     // per-layer storage scale s = 1/16
#define UNSCALE 4294967296.0f           // s^-8 = 2^32 (exact fp32)

#define NCHUNKS_TOT 40
#define CHUNK_ELEMS 16384

// ---------------- scratch (no cudaMalloc allowed) ----------------
__device__ __align__(16) __half g_hh[(size_t)NN * HH];    // scaled h, fp16
__device__ __align__(16) __half g_x0h[(size_t)NN * HH];   // x0, fp16
__device__ __align__(16) __half g_mixh[(size_t)NN * HH];  // scaled mix, fp16
__device__ int    g_rowptr[NN + 1];
__device__ int    g_cnt[NN];
__device__ int    g_col[EE];
__device__ float  g_val[EE];
__device__ __align__(16) uint16_t g_Bh[(size_t)NCHUNKS_TOT * CHUNK_ELEMS];
__device__ __align__(16) uint16_t g_Bl[(size_t)NCHUNKS_TOT * CHUNK_ELEMS];

// ---------------------------------------------------------------------------
__device__ __forceinline__ uint16_t f16_bits(float v) {
    __half h = __float2half_rn(v);
    return *reinterpret_cast<uint16_t*>(&h);
}
__device__ __forceinline__ float f16_val(uint16_t u) {
    __half h = *reinterpret_cast<__half*>(&u);
    return __half2float(h);
}

// fp16 HMMA m16n8k16, fp32 accum
__device__ __forceinline__ void mma16816(float* d, const uint32_t* a,
                                         uint32_t b0, uint32_t b1) {
    asm volatile(
        "mma.sync.aligned.m16n8k16.row.col.f32.f16.f16.f32 "
        "{%0,%1,%2,%3}, {%4,%5,%6,%7}, {%8,%9}, {%0,%1,%2,%3};"
        : "+f"(d[0]), "+f"(d[1]), "+f"(d[2]), "+f"(d[3])
        : "r"(a[0]), "r"(a[1]), "r"(a[2]), "r"(a[3]), "r"(b0), "r"(b1));
}

// ---------------------------------------------------------------------------
// B chunk library (fp16 hi/lo): chunks 0..7 = W_in; 8+4l+c = beta*W_l+(1-beta)I
// ---------------------------------------------------------------------------
__global__ void prep_B_kernel(const float* __restrict__ Win,
                              const float* __restrict__ convW,
                              uint16_t* __restrict__ Bh, uint16_t* __restrict__ Bl)
{
    int e = blockIdx.x * 256 + threadIdx.x;
    if (e >= NCHUNKS_TOT * CHUNK_ELEMS) return;
    int chunk = e >> 14, w = e & 16383;
    int n = w >> 6, kk = w & 63;
    float val;
    if (chunk < 8) {
        val = __ldg(&Win[(chunk * 64 + kk) * HH + n]);
    } else {
        int l = (chunk - 8) >> 2, c = (chunk - 8) & 3, k = c * 64 + kk;
        float beta = logf(0.5f / (float)(l + 1) + 1.0f);
        val = beta * __ldg(&convW[(size_t)l * HH * HH + (size_t)k * HH + n]);
        if (k == n) val += 1.0f - beta;
    }
    uint16_t hi = f16_bits(val);
    uint16_t lo = f16_bits(val - f16_val(hi));
    Bh[e] = hi;
    Bl[e] = lo;
}

// ---------------------------------------------------------------------------
#define LDP 72
#define SA_ELEMS (128 * LDP)

// Input GEMM: A fp32 [M,512] -> fp16 hi/lo split, 3 terms.
// Writes Ch (h fp16) + C2 (x0 fp16).
__global__ __launch_bounds__(256, 2)
void mma_gemm_in(const float* __restrict__ A,
                 const uint16_t* __restrict__ Bh, const uint16_t* __restrict__ Bl,
                 const float* __restrict__ bias,
                 __half* __restrict__ Ch, __half* __restrict__ C2, int M)
{
    extern __shared__ uint16_t sm[];
    uint16_t* sAh = sm;
    uint16_t* sAl = sm + SA_ELEMS;
    uint16_t* sBh = sm + 2 * SA_ELEMS;
    uint16_t* sBl = sm + 3 * SA_ELEMS;

    const int tid = threadIdx.x;
    const int warp = tid >> 5, lane = tid & 31;
    const int wm = warp >> 1, wn = warp & 1;
    const int g = lane >> 2, t = lane & 3;
    const int row0 = blockIdx.y * 128;
    const int col0 = blockIdx.x * 128;

    float acc[2][8][4];
#pragma unroll
    for (int mi = 0; mi < 2; mi++)
#pragma unroll
        for (int ni = 0; ni < 8; ni++)
#pragma unroll
            for (int q = 0; q < 4; q++) acc[mi][ni][q] = 0.f;

    for (int c = 0; c < 8; c++) {
        __syncthreads();
#pragma unroll
        for (int i = 0; i < 8; i++) {
            int f = tid + i * 256;
            int r = f >> 4, kq = (f & 15) * 4;
            float4 v = make_float4(0.f, 0.f, 0.f, 0.f);
            if (row0 + r < M)
                v = *(const float4*)(A + (size_t)(row0 + r) * FIN + c * 64 + kq);
            uint16_t h0 = f16_bits(v.x), h1 = f16_bits(v.y);
            uint16_t h2 = f16_bits(v.z), h3 = f16_bits(v.w);
            uint16_t l0 = f16_bits(v.x - f16_val(h0));
            uint16_t l1 = f16_bits(v.y - f16_val(h1));
            uint16_t l2 = f16_bits(v.z - f16_val(h2));
            uint16_t l3 = f16_bits(v.w - f16_val(h3));
            int base = r * LDP + kq;
            *(uint32_t*)&sAh[base]     = (uint32_t)h0 | ((uint32_t)h1 << 16);
            *(uint32_t*)&sAh[base + 2] = (uint32_t)h2 | ((uint32_t)h3 << 16);
            *(uint32_t*)&sAl[base]     = (uint32_t)l0 | ((uint32_t)l1 << 16);
            *(uint32_t*)&sAl[base + 2] = (uint32_t)l2 | ((uint32_t)l3 << 16);
        }
        {
            const size_t cb = ((size_t)c << 14) + (size_t)col0 * 64;
#pragma unroll
            for (int i = 0; i < 4; i++) {
                int f = tid + i * 256;
                int n = f >> 3, k8 = (f & 7) * 8;
                *(uint4*)&sBh[n * LDP + k8] = *(const uint4*)(Bh + cb + n * 64 + k8);
                *(uint4*)&sBl[n * LDP + k8] = *(const uint4*)(Bl + cb + n * 64 + k8);
            }
        }
        __syncthreads();

#pragma unroll
        for (int ks = 0; ks < 4; ks++) {
            uint32_t ah[2][4], al[2][4];
#pragma unroll
            for (int mi = 0; mi < 2; mi++) {
                int base = (wm * 32 + mi * 16 + g) * LDP + ks * 16 + 2 * t;
                ah[mi][0] = *(const uint32_t*)&sAh[base];
                ah[mi][1] = *(const uint32_t*)&sAh[base + 8 * LDP];
                ah[mi][2] = *(const uint32_t*)&sAh[base + 8];
                ah[mi][3] = *(const uint32_t*)&sAh[base + 8 * LDP + 8];
                al[mi][0] = *(const uint32_t*)&sAl[base];
                al[mi][1] = *(const uint32_t*)&sAl[base + 8 * LDP];
                al[mi][2] = *(const uint32_t*)&sAl[base + 8];
                al[mi][3] = *(const uint32_t*)&sAl[base + 8 * LDP + 8];
            }
#pragma unroll
            for (int ni = 0; ni < 8; ni++) {
                int bb = (wn * 64 + ni * 8 + g) * LDP + ks * 16 + 2 * t;
                uint32_t bh0 = *(const uint32_t*)&sBh[bb];
                uint32_t bh1 = *(const uint32_t*)&sBh[bb + 8];
                uint32_t bl0 = *(const uint32_t*)&sBl[bb];
                uint32_t bl1 = *(const uint32_t*)&sBl[bb + 8];
#pragma unroll
                for (int mi = 0; mi < 2; mi++) {
                    mma16816(acc[mi][ni], ah[mi], bh0, bh1);
                    mma16816(acc[mi][ni], ah[mi], bl0, bl1);
                    mma16816(acc[mi][ni], al[mi], bh0, bh1);
                }
            }
        }
    }

#pragma unroll
    for (int mi = 0; mi < 2; mi++) {
        int r0 = row0 + wm * 32 + mi * 16 + g;
#pragma unroll
        for (int half_ = 0; half_ < 2; half_++) {
            int r = r0 + half_ * 8;
            if (r >= M) continue;
#pragma unroll
            for (int ni = 0; ni < 8; ni++) {
                int cg = col0 + wn * 64 + ni * 8 + 2 * t;
                float v0 = acc[mi][ni][half_ * 2 + 0] + __ldg(&bias[cg]);
                float v1 = acc[mi][ni][half_ * 2 + 1] + __ldg(&bias[cg + 1]);
                v0 = fminf(fmaxf(v0, 0.f), 65504.f);
                v1 = fminf(fmaxf(v1, 0.f), 65504.f);
                __half2 o = __floats2half2_rn(v0, v1);
                *(__half2*)(Ch + (size_t)r * HH + cg) = o;
                *(__half2*)(C2 + (size_t)r * HH + cg) = o;
            }
        }
    }
}

// ---------------------------------------------------------------------------
// Layer GEMM: A fp16 [M,256] used DIRECTLY (exact); B fp16 hi/lo, 2 terms.
// smem: sA + sBh + sBl = 3 buffers.
// ---------------------------------------------------------------------------
__global__ __launch_bounds__(256, 2)
void mma_gemm_h(const __half* __restrict__ A,
                const uint16_t* __restrict__ Bh, const uint16_t* __restrict__ Bl,
                int chunk0,
                __half* __restrict__ Ch, int M)
{
    extern __shared__ uint16_t sm[];
    uint16_t* sA  = sm;
    uint16_t* sBh = sm + SA_ELEMS;
    uint16_t* sBl = sm + 2 * SA_ELEMS;

    const int tid = threadIdx.x;
    const int warp = tid >> 5, lane = tid & 31;
    const int wm = warp >> 1, wn = warp & 1;
    const int g = lane >> 2, t = lane & 3;
    const int row0 = blockIdx.y * 128;
    const int col0 = blockIdx.x * 128;

    float acc[2][8][4];
#pragma unroll
    for (int mi = 0; mi < 2; mi++)
#pragma unroll
        for (int ni = 0; ni < 8; ni++)
#pragma unroll
            for (int q = 0; q < 4; q++) acc[mi][ni][q] = 0.f;

    for (int c = 0; c < 4; c++) {
        __syncthreads();
        // A chunk: 128 rows x 64 k fp16 -> straight copy (1024 uint4)
#pragma unroll
        for (int i = 0; i < 4; i++) {
            int f = tid + i * 256;
            int r = f >> 3, k8 = (f & 7) * 8;
            uint4 q = make_uint4(0, 0, 0, 0);
            if (row0 + r < M)
                q = *(const uint4*)(A + (size_t)(row0 + r) * HH + c * 64 + k8);
            *(uint4*)&sA[r * LDP + k8] = q;
        }
        {
            const size_t cb = ((size_t)(chunk0 + c) << 14) + (size_t)col0 * 64;
#pragma unroll
            for (int i = 0; i < 4; i++) {
                int f = tid + i * 256;
                int n = f >> 3, k8 = (f & 7) * 8;
                *(uint4*)&sBh[n * LDP + k8] = *(const uint4*)(Bh + cb + n * 64 + k8);
                *(uint4*)&sBl[n * LDP + k8] = *(const uint4*)(Bl + cb + n * 64 + k8);
            }
        }
        __syncthreads();

#pragma unroll
        for (int ks = 0; ks < 4; ks++) {
            uint32_t ar[2][4];
#pragma unroll
            for (int mi = 0; mi < 2; mi++) {
                int base = (wm * 32 + mi * 16 + g) * LDP + ks * 16 + 2 * t;
                ar[mi][0] = *(const uint32_t*)&sA[base];
                ar[mi][1] = *(const uint32_t*)&sA[base + 8 * LDP];
                ar[mi][2] = *(const uint32_t*)&sA[base + 8];
                ar[mi][3] = *(const uint32_t*)&sA[base + 8 * LDP + 8];
            }
#pragma unroll
            for (int ni = 0; ni < 8; ni++) {
                int bb = (wn * 64 + ni * 8 + g) * LDP + ks * 16 + 2 * t;
                uint32_t bh0 = *(const uint32_t*)&sBh[bb];
                uint32_t bh1 = *(const uint32_t*)&sBh[bb + 8];
                uint32_t bl0 = *(const uint32_t*)&sBl[bb];
                uint32_t bl1 = *(const uint32_t*)&sBl[bb + 8];
#pragma unroll
                for (int mi = 0; mi < 2; mi++) {
                    mma16816(acc[mi][ni], ar[mi], bh0, bh1);
                    mma16816(acc[mi][ni], ar[mi], bl0, bl1);
                }
            }
        }
    }

#pragma unroll
    for (int mi = 0; mi < 2; mi++) {
        int r0 = row0 + wm * 32 + mi * 16 + g;
#pragma unroll
        for (int half_ = 0; half_ < 2; half_++) {
            int r = r0 + half_ * 8;
            if (r >= M) continue;
#pragma unroll
            for (int ni = 0; ni < 8; ni++) {
                int cg = col0 + wn * 64 + ni * 8 + 2 * t;
                float v0 = fminf(fmaxf(acc[mi][ni][half_ * 2 + 0], 0.f), 65504.f);
                float v1 = fminf(fmaxf(acc[mi][ni][half_ * 2 + 1], 0.f), 65504.f);
                *(__half2*)(Ch + (size_t)r * HH + cg) = __floats2half2_rn(v0, v1);
            }
        }
    }
}

// ---------------------------------------------------------------------------
// CSR build
// ---------------------------------------------------------------------------
__global__ void hist_kernel(const int* __restrict__ erow, int* __restrict__ cnt, int E)
{
    for (int e = blockIdx.x * blockDim.x + threadIdx.x; e < E;
         e += gridDim.x * blockDim.x)
        atomicAdd(&cnt[__ldg(&erow[e])], 1);
}

__global__ __launch_bounds__(1024)
void scan_kernel(const int* __restrict__ cnt, int* __restrict__ rowptr)
{
    __shared__ int warpsums[32];
    __shared__ int running;
    int tid = threadIdx.x, lane = tid & 31, wid = tid >> 5;
    if (tid == 0) running = 0;
    __syncthreads();
    for (int base = 0; base < NN; base += 1024) {
        int v = (base + tid < NN) ? cnt[base + tid] : 0;
        int x = v;
#pragma unroll
        for (int o = 1; o < 32; o <<= 1) {
            int t = __shfl_up_sync(0xffffffffu, x, o);
            if (lane >= o) x += t;
        }
        if (lane == 31) warpsums[wid] = x;
        __syncthreads();
        if (wid == 0) {
            int s = warpsums[lane];
#pragma unroll
            for (int o = 1; o < 32; o <<= 1) {
                int t = __shfl_up_sync(0xffffffffu, s, o);
                if (lane >= o) s += t;
            }
            warpsums[lane] = s;
        }
        __syncthreads();
        int incl = x + (wid > 0 ? warpsums[wid - 1] : 0) + running;
        if (base + tid < NN) rowptr[base + tid + 1] = incl;
        __syncthreads();
        if (tid == 1023) running = incl;
        __syncthreads();
    }
    if (tid == 0) rowptr[0] = 0;
}

__global__ void scatter_kernel(const int* __restrict__ erow,
                               const int* __restrict__ ecol,
                               const float* __restrict__ eval,
                               const int* __restrict__ rowptr,
                               int* __restrict__ cnt,
                               int* __restrict__ csr_col,
                               float* __restrict__ csr_val, int E)
{
    for (int e = blockIdx.x * blockDim.x + threadIdx.x; e < E;
         e += gridDim.x * blockDim.x) {
        int r = __ldg(&erow[e]);
        int p = __ldg(&rowptr[r]) + atomicAdd(&cnt[r], 1);
        csr_col[p] = __ldg(&ecol[e]);
        csr_val[p] = __ldg(&eval[e]) * ((1.0f - ALPHA) * SCL);
    }
}

// ---------------------------------------------------------------------------
// CSR SpMM: fp16 gather + fp16 x0, fp32 accum, fp16 mix out. Warp per row.
// ---------------------------------------------------------------------------
__global__ __launch_bounds__(256)
void spmm_half_kernel(const int* __restrict__ rowptr,
                      const int* __restrict__ cols,
                      const float* __restrict__ vals,
                      const __half* __restrict__ h,
                      const __half* __restrict__ x0h,
                      __half* __restrict__ mix, float x0c, int M)
{
    int row = (blockIdx.x * 256 + threadIdx.x) >> 5;
    int lane = threadIdx.x & 31;
    if (row >= M) return;

    int s = __ldg(&rowptr[row]);
    int e = __ldg(&rowptr[row + 1]);

    float acc[8];
    {
        uint4 q = __ldg((const uint4*)(x0h + (size_t)row * HH) + lane);
        float2 f0 = __half22float2(*reinterpret_cast<__half2*>(&q.x));
        float2 f1 = __half22float2(*reinterpret_cast<__half2*>(&q.y));
        float2 f2 = __half22float2(*reinterpret_cast<__half2*>(&q.z));
        float2 f3 = __half22float2(*reinterpret_cast<__half2*>(&q.w));
        acc[0] = x0c * f0.x; acc[1] = x0c * f0.y;
        acc[2] = x0c * f1.x; acc[3] = x0c * f1.y;
        acc[4] = x0c * f2.x; acc[5] = x0c * f2.y;
        acc[6] = x0c * f3.x; acc[7] = x0c * f3.y;
    }

    int i = s;
#define GATH(cc, vv) do {                                                  \
        uint4 q = __ldg((const uint4*)(h + (size_t)(cc) * HH) + lane);     \
        float2 f0 = __half22float2(*reinterpret_cast<__half2*>(&q.x));     \
        float2 f1 = __half22float2(*reinterpret_cast<__half2*>(&q.y));     \
        float2 f2 = __half22float2(*reinterpret_cast<__half2*>(&q.z));     \
        float2 f3 = __half22float2(*reinterpret_cast<__half2*>(&q.w));     \
        acc[0] += (vv) * f0.x; acc[1] += (vv) * f0.y;                      \
        acc[2] += (vv) * f1.x; acc[3] += (vv) * f1.y;                      \
        acc[4] += (vv) * f2.x; acc[5] += (vv) * f2.y;                      \
        acc[6] += (vv) * f3.x; acc[7] += (vv) * f3.y;                      \
    } while (0)

    for (; i + 4 <= e; i += 4) {
        int   c0 = __ldg(&cols[i]),     c1 = __ldg(&cols[i + 1]);
        int   c2 = __ldg(&cols[i + 2]), c3 = __ldg(&cols[i + 3]);
        float v0 = __ldg(&vals[i]),     v1 = __ldg(&vals[i + 1]);
        float v2 = __ldg(&vals[i + 2]), v3 = __ldg(&vals[i + 3]);
        GATH(c0, v0); GATH(c1, v1); GATH(c2, v2); GATH(c3, v3);
    }
    for (; i < e; i++) {
        int c = __ldg(&cols[i]);
        float v = __ldg(&vals[i]);
        GATH(c, v);
    }
#undef GATH

    uint4 o;
    __half2* op = reinterpret_cast<__half2*>(&o);
#pragma unroll
    for (int j = 0; j < 4; j++) {
        float a0 = fminf(fmaxf(acc[2 * j + 0], -65504.f), 65504.f);
        float a1 = fminf(fmaxf(acc[2 * j + 1], -65504.f), 65504.f);
        op[j] = __floats2half2_rn(a0, a1);
    }
    *((uint4*)(mix + (size_t)row * HH) + lane) = o;
}

// ---------------------------------------------------------------------------
// Output head: logits = UNSCALE*(h_scaled @ W_out) + b, then log_softmax.
// ---------------------------------------------------------------------------
__global__ __launch_bounds__(256)
void out_kernel(const __half* __restrict__ h, const float* __restrict__ W,
                const float* __restrict__ b, float* __restrict__ out, int M)
{
    __shared__ float hs[8][HH];
    int tid = threadIdx.x;
    int warp = tid >> 5, lane = tid & 31;
    int row = blockIdx.x * 8 + warp;

    if (row < M) {
        const uint4* hp = (const uint4*)(h + (size_t)row * HH);
        uint4 q = __ldg(&hp[lane]);
        float2 f0 = __half22float2(*reinterpret_cast<__half2*>(&q.x));
        float2 f1 = __half22float2(*reinterpret_cast<__half2*>(&q.y));
        float2 f2 = __half22float2(*reinterpret_cast<__half2*>(&q.z));
        float2 f3 = __half22float2(*reinterpret_cast<__half2*>(&q.w));
        int base = lane * 8;
        hs[warp][base + 0] = f0.x; hs[warp][base + 1] = f0.y;
        hs[warp][base + 2] = f1.x; hs[warp][base + 3] = f1.y;
        hs[warp][base + 4] = f2.x; hs[warp][base + 5] = f2.y;
        hs[warp][base + 6] = f3.x; hs[warp][base + 7] = f3.y;
    }
    __syncthreads();
    if (row >= M) return;

    float l0 = 0.f, l1 = 0.f;
#pragma unroll 8
    for (int k = 0; k < HH; k++) {
        float hv = hs[warp][k];
        l0 += hv * __ldg(&W[k * CC + lane]);
        l1 += hv * __ldg(&W[k * CC + lane + 32]);
    }
    l0 = l0 * UNSCALE + __ldg(&b[lane]);
    l1 = l1 * UNSCALE + __ldg(&b[lane + 32]);
    float m = fmaxf(l0, l1);
#pragma unroll
    for (int o = 16; o; o >>= 1) m = fmaxf(m, __shfl_xor_sync(0xffffffffu, m, o));
    float s = expf(l0 - m) + expf(l1 - m);
#pragma unroll
    for (int o = 16; o; o >>= 1) s += __shfl_xor_sync(0xffffffffu, s, o);
    float lse = m + logf(s);
    out[(size_t)row * CC + lane] = l0 - lse;
    out[(size_t)row * CC + lane + 32] = l1 - lse;
}

// ---------------------------------------------------------------------------
extern "C" void kernel_launch(void* const* d_in, const int* in_sizes, int n_in,
                              void* d_out, int out_size)
{
    const float* x        = (const float*)d_in[0];
    const float* edge_val = (const float*)d_in[1];
    const float* W_in     = (const float*)d_in[2];
    const float* b_in     = (const float*)d_in[3];
    const float* conv_W   = (const float*)d_in[4];
    const float* W_out    = (const float*)d_in[5];
    const float* b_out    = (const float*)d_in[6];
    const int*   erow     = (const int*)d_in[7];
    const int*   ecol     = (const int*)d_in[8];
    float* out = (float*)d_out;

    __half *hh, *x0h, *mixh;
    float *csr_val;
    int *rowptr, *cnt, *csr_col;
    uint16_t *Bh, *Bl;
    cudaGetSymbolAddress((void**)&hh,      g_hh);
    cudaGetSymbolAddress((void**)&x0h,     g_x0h);
    cudaGetSymbolAddress((void**)&mixh,    g_mixh);
    cudaGetSymbolAddress((void**)&rowptr,  g_rowptr);
    cudaGetSymbolAddress((void**)&cnt,     g_cnt);
    cudaGetSymbolAddress((void**)&csr_col, g_col);
    cudaGetSymbolAddress((void**)&csr_val, g_val);
    cudaGetSymbolAddress((void**)&Bh,      g_Bh);
    cudaGetSymbolAddress((void**)&Bl,      g_Bl);

    const int smem_in = 4 * SA_ELEMS * sizeof(uint16_t);   // 73728
    const int smem_h  = 3 * SA_ELEMS * sizeof(uint16_t);   // 55296
    cudaFuncSetAttribute(mma_gemm_in,
                         cudaFuncAttributeMaxDynamicSharedMemorySize, smem_in);
    cudaFuncSetAttribute(mma_gemm_h,
                         cudaFuncAttributeMaxDynamicSharedMemorySize, smem_h);

    dim3 gemm_grid(2, (NN + 127) / 128);   // (2, 782)

    // ---- B library + CSR build (per replay, deterministic) ----
    prep_B_kernel<<<(NCHUNKS_TOT * CHUNK_ELEMS + 255) / 256, 256>>>(
        W_in, conv_W, Bh, Bl);
    cudaMemsetAsync(cnt, 0, NN * sizeof(int));
    hist_kernel<<<592, 256>>>(erow, cnt, EE);
    scan_kernel<<<1, 1024>>>(cnt, rowptr);
    cudaMemsetAsync(cnt, 0, NN * sizeof(int));
    scatter_kernel<<<592, 256>>>(erow, ecol, edge_val, rowptr, cnt,
                                 csr_col, csr_val, EE);

    // ---- h0 = relu(x @ W_in + b_in) -> hh (fp16), x0h (fp16) ----
    mma_gemm_in<<<gemm_grid, 256, smem_in>>>(x, Bh, Bl, b_in, hh, x0h, NN);

    for (int l = 0; l < LL; l++) {
        float x0c = ALPHA * ldexpf(1.0f, -4 * (l + 1));   // alpha * s^{l+1}
        // mix(fp16) = x0c*x0 + (0.9*s)*A @ h
        spmm_half_kernel<<<(NN * 32 + 255) / 256, 256>>>(rowptr, csr_col,
                                                         csr_val, hh, x0h,
                                                         mixh, x0c, NN);
        // h(fp16) = relu( mix @ ((1-beta)I + beta*W_l) )  -- 2-term fp16 MMA
        mma_gemm_h<<<gemm_grid, 256, smem_h>>>(mixh, Bh, Bl, 8 + 4 * l,
                                               hh, NN);
    }

    out_kernel<<<(NN + 7) / 8, 256>>>(hh, W_out, b_out, out, NN);
}